// round 17
// baseline (speedup 1.0000x reference)
#include <cuda_runtime.h>
#include <cuda_bf16.h>
#include <cstdint>

// Problem constants: B=4, C=512, H=W=64 -> N=4096, CI=256
#define NB   4
#define NC   512
#define NN_  4096
#define NCI  256
typedef __nv_bfloat16 bf16;

// ---------------------------------------------------------------------------
// Scratch (device globals: allocation inside kernel_launch is forbidden)
// ---------------------------------------------------------------------------
__device__ bf16  g_wch [768 * NC];                 // concat [w_phi;w_theta;w_g] hi
__device__ bf16  g_wcl [768 * NC];                 // lo residual
__device__ bf16  g_wmh [NC * NCI];                 // w_mask hi/lo
__device__ bf16  g_wml [NC * NCI];
__device__ bf16  g_xh  [NB * NC * NN_];            // x (b,c,n) hi/lo
__device__ bf16  g_xl  [NB * NC * NN_];
__device__ float g_ptg [NB * 3 * NCI * NN_];       // phi/theta/g fp32 (b,768,4096)
__device__ float g_f   [(long long)NB * NN_ * NN_]; // scores/probs (268 MB)
__device__ bf16  g_yh  [NB * NCI * NN_];           // y hi/lo (b,ci,n)
__device__ bf16  g_yl  [NB * NCI * NN_];

// ---------------------------------------------------------------------------
// Helpers (legacy mma.sync path — tcgen05 unreachable: harness PTX target is
// sm_103 without the 'a' suffix, R12 finding)
// ---------------------------------------------------------------------------
__device__ __forceinline__ uint32_t f2tf32(float f) {
    uint32_t r;
    asm("cvt.rna.tf32.f32 %0, %1;" : "=r"(r) : "f"(f));
    return r;
}
__device__ __forceinline__ void mma8(float* d, const uint32_t* a, const uint32_t* b) {
    asm volatile(
        "mma.sync.aligned.m16n8k8.row.col.f32.tf32.tf32.f32 "
        "{%0,%1,%2,%3}, {%4,%5,%6,%7}, {%8,%9}, {%0,%1,%2,%3};"
        : "+f"(d[0]), "+f"(d[1]), "+f"(d[2]), "+f"(d[3])
        : "r"(a[0]), "r"(a[1]), "r"(a[2]), "r"(a[3]), "r"(b[0]), "r"(b[1]));
}
__device__ __forceinline__ void mma16bf(float* d, const uint32_t* a, const uint32_t* b) {
    asm volatile(
        "mma.sync.aligned.m16n8k16.row.col.f32.bf16.bf16.f32 "
        "{%0,%1,%2,%3}, {%4,%5,%6,%7}, {%8,%9}, {%0,%1,%2,%3};"
        : "+f"(d[0]), "+f"(d[1]), "+f"(d[2]), "+f"(d[3])
        : "r"(a[0]), "r"(a[1]), "r"(a[2]), "r"(a[3]), "r"(b[0]), "r"(b[1]));
}
// fp32 pair -> bf16x2 hi word + lo-residual word (even elem in low half)
__device__ __forceinline__ void pack_hl(float x, float y, uint32_t& ph, uint32_t& pl) {
    bf16 hx = __float2bfloat16(x), hy = __float2bfloat16(y);
    bf16 lx = __float2bfloat16(x - __bfloat162float(hx));
    bf16 ly = __float2bfloat16(y - __bfloat162float(hy));
    __nv_bfloat162 h2 = __halves2bfloat162(hx, hy);
    __nv_bfloat162 l2 = __halves2bfloat162(lx, ly);
    ph = *(uint32_t*)&h2;
    pl = *(uint32_t*)&l2;
}

// ---------------------------------------------------------------------------
// Prep: split weights + x into bf16 hi/lo ONCE (removes all conversion work
// from GEMM hot loops; wcat was re-converted 128x, x 6x, w_mask 128x, y 4x)
// ---------------------------------------------------------------------------
__global__ void prep_w(const float* __restrict__ wp, const float* __restrict__ wt,
                       const float* __restrict__ wg, const float* __restrict__ wm) {
    int i = blockIdx.x * 256 + threadIdx.x;          // 524288
    if (i < 393216) {
        float v = (i < 131072) ? wp[i] : (i < 262144 ? wt[i - 131072] : wg[i - 262144]);
        bf16 h = __float2bfloat16(v);
        g_wch[i] = h;
        g_wcl[i] = __float2bfloat16(v - __bfloat162float(h));
    } else {
        int j = i - 393216;
        float v = wm[j];
        bf16 h = __float2bfloat16(v);
        g_wmh[j] = h;
        g_wml[j] = __float2bfloat16(v - __bfloat162float(h));
    }
}
__global__ void prep_x(const float* __restrict__ x) {
    long long i = (long long)(blockIdx.x * 256 + threadIdx.x) * 4;   // 8192 blocks
    float4 v = *(const float4*)(x + i);
    uint32_t h0, l0, h1, l1;
    pack_hl(v.x, v.y, h0, l0);
    pack_hl(v.z, v.w, h1, l1);
    *(uint2*)&g_xh[i] = make_uint2(h0, h1);
    *(uint2*)&g_xl[i] = make_uint2(l0, l1);
}

// ---------------------------------------------------------------------------
// TF32 tensor-core GEMM (R9 core). EMIT=0: fp32 C. EMIT=1: bf16 hi/lo C
// (fuses the split for the downstream bf3 consumer).
//   A_KC : A is (M,K) row-major. Else (K,M) rm.
//   B_NC : B is (K,N) row-major. Else (N,K) rm.
// ---------------------------------------------------------------------------
template <bool A_KC, bool B_NC, int EMIT>
__global__ void __launch_bounds__(256, 2)
tc_gemm(const float* __restrict__ A, const float* __restrict__ B,
        float* __restrict__ C, bf16* __restrict__ Ch, bf16* __restrict__ Cl,
        int M, int Nn, int K,
        int lda, int ldb, int ldc,
        long long sA, long long sB, long long sC)
{
    __shared__ uint32_t As[2][16][136];
    __shared__ uint32_t Bs[2][16][136];

    const int t    = threadIdx.x;
    const int lane = t & 31;
    const int wid  = t >> 5;
    const int wm   = wid >> 2;
    const int wn   = wid & 3;
    const int g    = lane >> 2;
    const int tg   = lane & 3;

    A += (long long)blockIdx.z * sA;
    B += (long long)blockIdx.z * sB;

    const int m0 = blockIdx.y * 128;
    const int n0 = blockIdx.x * 128;

    long long aoff0, aoff1, boff0, boff1, aStep, bStep;
    if (A_KC) {
        int m_ = t >> 2, k4 = (t & 3) * 4;
        aoff0 = (long long)(m0 + m_) * lda + k4;
        aoff1 = (long long)(m0 + m_ + 64) * lda + k4;
        aStep = 16;
    } else {
        int kr = t >> 5, m4 = (t & 31) * 4;
        aoff0 = (long long)kr * lda + m0 + m4;
        aoff1 = (long long)(kr + 8) * lda + m0 + m4;
        aStep = 16LL * lda;
    }
    if (B_NC) {
        int kr = t >> 5, n4 = (t & 31) * 4;
        boff0 = (long long)kr * ldb + n0 + n4;
        boff1 = (long long)(kr + 8) * ldb + n0 + n4;
        bStep = 16LL * ldb;
    } else {
        int n_ = t >> 2, k4 = (t & 3) * 4;
        boff0 = (long long)(n0 + n_) * ldb + k4;
        boff1 = (long long)(n0 + n_ + 64) * ldb + k4;
        bStep = 16;
    }

    auto storeA = [&](int buf, float4 v0, float4 v1) {
        if constexpr (A_KC) {
            int m_ = t >> 2, k4 = (t & 3) * 4;
            As[buf][k4 + 0][m_] = f2tf32(v0.x);
            As[buf][k4 + 1][m_] = f2tf32(v0.y);
            As[buf][k4 + 2][m_] = f2tf32(v0.z);
            As[buf][k4 + 3][m_] = f2tf32(v0.w);
            As[buf][k4 + 0][m_ + 64] = f2tf32(v1.x);
            As[buf][k4 + 1][m_ + 64] = f2tf32(v1.y);
            As[buf][k4 + 2][m_ + 64] = f2tf32(v1.z);
            As[buf][k4 + 3][m_ + 64] = f2tf32(v1.w);
        } else {
            int kr = t >> 5, m4 = (t & 31) * 4;
            uint4 u0 = make_uint4(f2tf32(v0.x), f2tf32(v0.y), f2tf32(v0.z), f2tf32(v0.w));
            uint4 u1 = make_uint4(f2tf32(v1.x), f2tf32(v1.y), f2tf32(v1.z), f2tf32(v1.w));
            *(uint4*)&As[buf][kr][m4]     = u0;
            *(uint4*)&As[buf][kr + 8][m4] = u1;
        }
    };
    auto storeB = [&](int buf, float4 v0, float4 v1) {
        if constexpr (B_NC) {
            int kr = t >> 5, n4 = (t & 31) * 4;
            uint4 u0 = make_uint4(f2tf32(v0.x), f2tf32(v0.y), f2tf32(v0.z), f2tf32(v0.w));
            uint4 u1 = make_uint4(f2tf32(v1.x), f2tf32(v1.y), f2tf32(v1.z), f2tf32(v1.w));
            *(uint4*)&Bs[buf][kr][n4]     = u0;
            *(uint4*)&Bs[buf][kr + 8][n4] = u1;
        } else {
            int n_ = t >> 2, k4 = (t & 3) * 4;
            Bs[buf][k4 + 0][n_] = f2tf32(v0.x);
            Bs[buf][k4 + 1][n_] = f2tf32(v0.y);
            Bs[buf][k4 + 2][n_] = f2tf32(v0.z);
            Bs[buf][k4 + 3][n_] = f2tf32(v0.w);
            Bs[buf][k4 + 0][n_ + 64] = f2tf32(v1.x);
            Bs[buf][k4 + 1][n_ + 64] = f2tf32(v1.y);
            Bs[buf][k4 + 2][n_ + 64] = f2tf32(v1.z);
            Bs[buf][k4 + 3][n_ + 64] = f2tf32(v1.w);
        }
    };

    {
        float4 a0 = *(const float4*)(A + aoff0);
        float4 a1 = *(const float4*)(A + aoff1);
        float4 b0 = *(const float4*)(B + boff0);
        float4 b1 = *(const float4*)(B + boff1);
        storeA(0, a0, a1);
        storeB(0, b0, b1);
    }
    __syncthreads();

    float acc[4][4][4];
#pragma unroll
    for (int mi = 0; mi < 4; mi++)
#pragma unroll
        for (int ni = 0; ni < 4; ni++)
#pragma unroll
            for (int r = 0; r < 4; r++) acc[mi][ni][r] = 0.0f;

    const int nT = K >> 4;
    int buf = 0;

    for (int kt = 0; kt < nT; kt++) {
        const bool nxt = (kt + 1 < nT);
        float4 na0, na1, nb0, nb1;
        if (nxt) {
            aoff0 += aStep; aoff1 += aStep;
            boff0 += bStep; boff1 += bStep;
            na0 = *(const float4*)(A + aoff0);
            na1 = *(const float4*)(A + aoff1);
            nb0 = *(const float4*)(B + boff0);
            nb1 = *(const float4*)(B + boff1);
        }

#pragma unroll
        for (int kk = 0; kk < 16; kk += 8) {
            uint32_t afr[4][4], bfr[4][2];
#pragma unroll
            for (int mi = 0; mi < 4; mi++) {
                int mc = wm * 64 + mi * 16 + g;
                afr[mi][0] = As[buf][kk + tg][mc];
                afr[mi][1] = As[buf][kk + tg][mc + 8];
                afr[mi][2] = As[buf][kk + tg + 4][mc];
                afr[mi][3] = As[buf][kk + tg + 4][mc + 8];
            }
#pragma unroll
            for (int ni = 0; ni < 4; ni++) {
                int nc = wn * 32 + ni * 8 + g;
                bfr[ni][0] = Bs[buf][kk + tg][nc];
                bfr[ni][1] = Bs[buf][kk + tg + 4][nc];
            }
#pragma unroll
            for (int mi = 0; mi < 4; mi++)
#pragma unroll
                for (int ni = 0; ni < 4; ni++)
                    mma8(acc[mi][ni], afr[mi], bfr[ni]);
        }

        if (nxt) {
            storeA(buf ^ 1, na0, na1);
            storeB(buf ^ 1, nb0, nb1);
            __syncthreads();
            buf ^= 1;
        }
    }

#pragma unroll
    for (int mi = 0; mi < 4; mi++) {
#pragma unroll
        for (int ni = 0; ni < 4; ni++) {
            int row = m0 + wm * 64 + mi * 16 + g;
            int col = n0 + wn * 32 + ni * 8 + 2 * tg;
            if constexpr (EMIT == 0) {
                float* Cb = C + (long long)blockIdx.z * sC;
                float2 lo = make_float2(acc[mi][ni][0], acc[mi][ni][1]);
                float2 hi = make_float2(acc[mi][ni][2], acc[mi][ni][3]);
                *(float2*)&Cb[(long long)row * ldc + col]       = lo;
                *(float2*)&Cb[(long long)(row + 8) * ldc + col] = hi;
            } else {
                bf16* Hb = Ch + (long long)blockIdx.z * sC;
                bf16* Lb = Cl + (long long)blockIdx.z * sC;
                uint32_t ph, pl;
                pack_hl(acc[mi][ni][0], acc[mi][ni][1], ph, pl);
                *(uint32_t*)&Hb[(long long)row * ldc + col] = ph;
                *(uint32_t*)&Lb[(long long)row * ldc + col] = pl;
                pack_hl(acc[mi][ni][2], acc[mi][ni][3], ph, pl);
                *(uint32_t*)&Hb[(long long)(row + 8) * ldc + col] = ph;
                *(uint32_t*)&Lb[(long long)(row + 8) * ldc + col] = pl;
            }
        }
    }
}

// ---------------------------------------------------------------------------
// BF16 3-term-split GEMM with PRE-SPLIT operands (no conversion in the loop):
// A (M,K) k-contig bf16 hi/lo; B (K,N) n-contig bf16 hi/lo. C fp32.
// acc += AhBh + AhBl + AlBh. Tile 128x128, BK=16, mma.m16n8k16.
// SMEM words = bf16x2 packed along k; A staging is a straight uint4 copy,
// B staging interleaves two k-rows via byte_perm.
// ---------------------------------------------------------------------------
__global__ void __launch_bounds__(256, 2)
tc_gemm_bf3p(const bf16* __restrict__ Ah, const bf16* __restrict__ Al,
             const bf16* __restrict__ Bh, const bf16* __restrict__ Bl,
             float* __restrict__ C, int M, int Nn, int K,
             int lda, int ldb, int ldc,
             long long sB, long long sC)
{
    __shared__ uint32_t Ash[2][8][136], Asl[2][8][136];
    __shared__ uint32_t Bsh[2][8][136], Bsl[2][8][136];

    const int t    = threadIdx.x;
    const int lane = t & 31;
    const int wid  = t >> 5;
    const int wm   = wid >> 2;
    const int wn   = wid & 3;
    const int g    = lane >> 2;
    const int tg   = lane & 3;

    Bh += (long long)blockIdx.z * sB;
    Bl += (long long)blockIdx.z * sB;
    C  += (long long)blockIdx.z * sC;

    const int m0 = blockIdx.y * 128;
    const int n0 = blockIdx.x * 128;

    // A: thread (m_, kp4): row m_, word-rows kp4..kp4+3 (8 consecutive k)
    const int a_m = t >> 1, a_kp = (t & 1) * 4;
    // B: thread (kp, n4): k-rows 2kp/2kp+1, 4 consecutive n
    const int b_kp = t >> 5, b_n4 = (t & 31) * 4;

    long long aoff  = (long long)(m0 + a_m) * lda + a_kp * 2;
    long long boffe = (long long)(2 * b_kp) * ldb + n0 + b_n4;
    const long long aStep = 16, bStep = 16LL * ldb;

    auto stage = [&](int buf, uint4 uh, uint4 ul, uint2 ehh, uint2 ohh, uint2 ehl, uint2 ohl) {
        Ash[buf][a_kp + 0][a_m] = uh.x; Ash[buf][a_kp + 1][a_m] = uh.y;
        Ash[buf][a_kp + 2][a_m] = uh.z; Ash[buf][a_kp + 3][a_m] = uh.w;
        Asl[buf][a_kp + 0][a_m] = ul.x; Asl[buf][a_kp + 1][a_m] = ul.y;
        Asl[buf][a_kp + 2][a_m] = ul.z; Asl[buf][a_kp + 3][a_m] = ul.w;
        Bsh[buf][b_kp][b_n4 + 0] = __byte_perm(ehh.x, ohh.x, 0x5410);
        Bsh[buf][b_kp][b_n4 + 1] = __byte_perm(ehh.x, ohh.x, 0x7632);
        Bsh[buf][b_kp][b_n4 + 2] = __byte_perm(ehh.y, ohh.y, 0x5410);
        Bsh[buf][b_kp][b_n4 + 3] = __byte_perm(ehh.y, ohh.y, 0x7632);
        Bsl[buf][b_kp][b_n4 + 0] = __byte_perm(ehl.x, ohl.x, 0x5410);
        Bsl[buf][b_kp][b_n4 + 1] = __byte_perm(ehl.x, ohl.x, 0x7632);
        Bsl[buf][b_kp][b_n4 + 2] = __byte_perm(ehl.y, ohl.y, 0x5410);
        Bsl[buf][b_kp][b_n4 + 3] = __byte_perm(ehl.y, ohl.y, 0x7632);
    };

    {
        uint4 uh = *(const uint4*)(Ah + aoff);
        uint4 ul = *(const uint4*)(Al + aoff);
        uint2 ehh = *(const uint2*)(Bh + boffe);
        uint2 ohh = *(const uint2*)(Bh + boffe + ldb);
        uint2 ehl = *(const uint2*)(Bl + boffe);
        uint2 ohl = *(const uint2*)(Bl + boffe + ldb);
        stage(0, uh, ul, ehh, ohh, ehl, ohl);
    }
    __syncthreads();

    float acc[4][4][4];
#pragma unroll
    for (int mi = 0; mi < 4; mi++)
#pragma unroll
        for (int ni = 0; ni < 4; ni++)
#pragma unroll
            for (int r = 0; r < 4; r++) acc[mi][ni][r] = 0.0f;

    const int nT = K >> 4;
    int buf = 0;

    for (int kt = 0; kt < nT; kt++) {
        const bool nxt = (kt + 1 < nT);
        uint4 uh, ul; uint2 ehh, ohh, ehl, ohl;
        if (nxt) {
            aoff += aStep; boffe += bStep;
            uh  = *(const uint4*)(Ah + aoff);
            ul  = *(const uint4*)(Al + aoff);
            ehh = *(const uint2*)(Bh + boffe);
            ohh = *(const uint2*)(Bh + boffe + ldb);
            ehl = *(const uint2*)(Bl + boffe);
            ohl = *(const uint2*)(Bl + boffe + ldb);
        }

        uint32_t ah[4][4], al[4][4], bh[4][2], bl[4][2];
#pragma unroll
        for (int mi = 0; mi < 4; mi++) {
            int mc = wm * 64 + mi * 16 + g;
            ah[mi][0] = Ash[buf][tg][mc];         al[mi][0] = Asl[buf][tg][mc];
            ah[mi][1] = Ash[buf][tg][mc + 8];     al[mi][1] = Asl[buf][tg][mc + 8];
            ah[mi][2] = Ash[buf][tg + 4][mc];     al[mi][2] = Asl[buf][tg + 4][mc];
            ah[mi][3] = Ash[buf][tg + 4][mc + 8]; al[mi][3] = Asl[buf][tg + 4][mc + 8];
        }
#pragma unroll
        for (int ni = 0; ni < 4; ni++) {
            int nc = wn * 32 + ni * 8 + g;
            bh[ni][0] = Bsh[buf][tg][nc];     bl[ni][0] = Bsl[buf][tg][nc];
            bh[ni][1] = Bsh[buf][tg + 4][nc]; bl[ni][1] = Bsl[buf][tg + 4][nc];
        }
#pragma unroll
        for (int mi = 0; mi < 4; mi++)
#pragma unroll
            for (int ni = 0; ni < 4; ni++) {
                mma16bf(acc[mi][ni], ah[mi], bh[ni]);
                mma16bf(acc[mi][ni], ah[mi], bl[ni]);
                mma16bf(acc[mi][ni], al[mi], bh[ni]);
            }

        if (nxt) {
            stage(buf ^ 1, uh, ul, ehh, ohh, ehl, ohl);
            __syncthreads();
            buf ^= 1;
        }
    }

#pragma unroll
    for (int mi = 0; mi < 4; mi++) {
#pragma unroll
        for (int ni = 0; ni < 4; ni++) {
            int row = m0 + wm * 64 + mi * 16 + g;
            int col = n0 + wn * 32 + ni * 8 + 2 * tg;
            float2 lo = make_float2(acc[mi][ni][0], acc[mi][ni][1]);
            float2 hi = make_float2(acc[mi][ni][2], acc[mi][ni][3]);
            *(float2*)&C[(long long)row * ldc + col]       = lo;
            *(float2*)&C[(long long)(row + 8) * ldc + col] = hi;
        }
    }
}

// ---------------------------------------------------------------------------
// Softmax over rows of 4096 (HBM-bound at ~80% — unchanged).
// ---------------------------------------------------------------------------
__device__ __forceinline__ float fast_exp(float x) {
    float t = x * 1.4426950408889634f;
    t = fmaxf(t, -126.0f);
    float fi = floorf(t);
    float fr = (t - fi) * 0.6931471805599453f;
    float p = 1.0f / 720.0f;
    p = fmaf(p, fr, 1.0f / 120.0f);
    p = fmaf(p, fr, 1.0f / 24.0f);
    p = fmaf(p, fr, 1.0f / 6.0f);
    p = fmaf(p, fr, 0.5f);
    p = fmaf(p, fr, 1.0f);
    p = fmaf(p, fr, 1.0f);
    return p * __int_as_float(((int)fi + 127) << 23);
}

__global__ void __launch_bounds__(256) softmax_kernel(float* __restrict__ f) {
    float* p = f + (long long)blockIdx.x * NN_;
    const int t = threadIdx.x;
    float v[16];
    float mx = -3.4e38f;
#pragma unroll
    for (int i = 0; i < 16; i++) {
        v[i] = p[i * 256 + t];
        mx = fmaxf(mx, v[i]);
    }
#pragma unroll
    for (int o = 16; o > 0; o >>= 1)
        mx = fmaxf(mx, __shfl_xor_sync(0xffffffffu, mx, o));
    __shared__ float sred[8];
    if ((t & 31) == 0) sred[t >> 5] = mx;
    __syncthreads();
#pragma unroll
    for (int i = 0; i < 8; i++) mx = fmaxf(mx, sred[i]);
    __syncthreads();

    float s = 0.0f;
#pragma unroll
    for (int i = 0; i < 16; i++) { v[i] = fast_exp(v[i] - mx); s += v[i]; }
#pragma unroll
    for (int o = 16; o > 0; o >>= 1)
        s += __shfl_xor_sync(0xffffffffu, s, o);
    if ((t & 31) == 0) sred[t >> 5] = s;
    __syncthreads();
    s = 0.0f;
#pragma unroll
    for (int i = 0; i < 8; i++) s += sred[i];

    const float inv = 1.0f / s;
#pragma unroll
    for (int i = 0; i < 16; i++) p[i * 256 + t] = v[i] * inv;
}

// ---------------------------------------------------------------------------
// kernel_launch: graph-capturable (kernel launches only; no sync, no alloc)
// ---------------------------------------------------------------------------
extern "C" void kernel_launch(void* const* d_in, const int* in_sizes, int n_in,
                              void* d_out, int out_size) {
    (void)in_sizes; (void)n_in; (void)out_size;
    const float* x       = (const float*)d_in[0];
    const float* w_phi   = (const float*)d_in[1];
    const float* w_theta = (const float*)d_in[2];
    const float* w_g     = (const float*)d_in[3];
    const float* w_mask  = (const float*)d_in[4];
    float* out = (float*)d_out;

    bf16 *wch, *wcl, *wmh, *wml, *xh, *xl, *yh, *yl;
    float *ptg, *f;
    cudaGetSymbolAddress((void**)&wch, g_wch); cudaGetSymbolAddress((void**)&wcl, g_wcl);
    cudaGetSymbolAddress((void**)&wmh, g_wmh); cudaGetSymbolAddress((void**)&wml, g_wml);
    cudaGetSymbolAddress((void**)&xh,  g_xh);  cudaGetSymbolAddress((void**)&xl,  g_xl);
    cudaGetSymbolAddress((void**)&yh,  g_yh);  cudaGetSymbolAddress((void**)&yl,  g_yl);
    cudaGetSymbolAddress((void**)&ptg, g_ptg);
    cudaGetSymbolAddress((void**)&f,   g_f);

    // 1) one-time splits
    prep_w<<<2048, 256>>>(w_phi, w_theta, w_g, w_mask);
    prep_x<<<8192, 256>>>(x);

    // 2) [phi;theta;g] = Wcat(768x512) @ x[b](512x4096)  (bf3, pre-split)
    tc_gemm_bf3p<<<dim3(32, 6, NB), 256>>>(
        wch, wcl, xh, xl, ptg, 768, NN_, NC,
        NC, NN_, NN_, (long long)NC * NN_, 768LL * NN_);

    // 3) f[n,m] = sum_c theta[c,n] * phi[c,m]   (tf32, fp32 out)
    tc_gemm<false, true, 0><<<dim3(32, 32, NB), 256>>>(
        ptg + NCI * NN_, ptg, f, nullptr, nullptr, NN_, NN_, NCI,
        NN_, NN_, NN_, 768LL * NN_, 768LL * NN_, (long long)NN_ * NN_);

    // 4) softmax over last axis, in place
    softmax_kernel<<<NB * NN_, 256>>>(f);

    // 5) y[c,n] = sum_m g[c,m] * a[n,m]   (tf32, bf16 hi/lo out for mask bf3)
    tc_gemm<true, false, 1><<<dim3(32, 2, NB), 256>>>(
        ptg + 2 * NCI * NN_, f, nullptr, yh, yl, NCI, NN_, NN_,
        NN_, NN_, NN_, 768LL * NN_, (long long)NN_ * NN_, (long long)NCI * NN_);

    // 6) out[o,n] = sum_c w_mask[o,c] * y[c,n]  (bf3, pre-split)
    tc_gemm_bf3p<<<dim3(32, 4, NB), 256>>>(
        wmh, wml, yh, yl, out, NC, NN_, NCI,
        NCI, NN_, NN_, (long long)NCI * NN_, (long long)NC * NN_);
}